// round 14
// baseline (speedup 1.0000x reference)
#include <cuda_runtime.h>
#include <cuda_fp16.h>
#include <cstdint>

#define Nn 20000
#define Ee 320000
#define TBE 16
#define TN  8

// ---------------- scratch (device globals; no allocation) ----------------
__device__ float g_maggr[Nn * 128];
__device__ float g_paggr[Nn * 128];
__device__ float g_deg[Nn];
__device__ float g_vij[(size_t)Ee * 128];
__device__ __half g_Sh[Nn * 128];
__device__ __half g_EA[(size_t)Ee * 64];
__device__ __half g_W1Thi[128 * 320], g_W1Tlo[128 * 320];
__device__ __half g_W2Thi[128 * 128], g_W2Tlo[128 * 128];
__device__ __half g_P1Thi[128 * 128], g_P1Tlo[128 * 128];

__constant__ int c_grade[8] = {0, 1, 1, 1, 2, 2, 2, 3};
__device__ constexpr int RES[8][8] = {
    {0,1,2,3,4,5,6,7},{1,0,4,5,2,3,7,6},{2,4,0,6,1,7,3,5},{3,5,6,0,7,1,2,4},
    {4,2,1,7,0,6,5,3},{5,3,7,1,6,0,4,2},{6,7,3,2,5,4,0,1},{7,6,5,4,3,2,1,0}};
__device__ constexpr float SGN[8][8] = {
    { 1, 1, 1, 1, 1, 1, 1, 1},{ 1, 1, 1, 1, 1, 1, 1, 1},
    { 1,-1, 1, 1,-1,-1, 1,-1},{ 1,-1,-1, 1, 1,-1,-1, 1},
    { 1,-1, 1, 1,-1,-1, 1,-1},{ 1,-1,-1, 1, 1,-1,-1, 1},
    { 1, 1,-1, 1,-1, 1,-1,-1},{ 1, 1,-1, 1,-1, 1,-1,-1}};

// ---------------- helpers ----------------
__device__ __forceinline__ uint32_t smem_u32(const void* p) {
    uint32_t a;
    asm("{ .reg .u64 t; cvta.to.shared.u64 t, %1; cvt.u32.u64 %0, t; }" : "=r"(a) : "l"(p));
    return a;
}
// 2 logical 64B rows packed per 128B physical row, SW128 XOR swizzle.
__device__ __forceinline__ uint32_t sw_off(int row, int kb) {
    uint32_t o = ((uint32_t)(row >> 1) << 7) | ((uint32_t)(row & 1) << 6) | (uint32_t)kb;
    return o ^ ((o >> 3) & 0x70);
}
__device__ __forceinline__ void ldsm_x4(uint32_t* r, uint32_t addr) {
    asm volatile("ldmatrix.sync.aligned.m8n8.x4.shared.b16 {%0,%1,%2,%3}, [%4];"
                 : "=r"(r[0]), "=r"(r[1]), "=r"(r[2]), "=r"(r[3]) : "r"(addr));
}
__device__ __forceinline__ void mma16816(float* c, const uint32_t* a, const uint32_t* b) {
    asm volatile("mma.sync.aligned.m16n8k16.row.col.f32.f16.f16.f32 "
                 "{%0,%1,%2,%3}, {%4,%5,%6,%7}, {%8,%9}, {%0,%1,%2,%3};"
                 : "+f"(c[0]), "+f"(c[1]), "+f"(c[2]), "+f"(c[3])
                 : "r"(a[0]), "r"(a[1]), "r"(a[2]), "r"(a[3]), "r"(b[0]), "r"(b[1]));
}
__device__ __forceinline__ void cpa16(uint32_t dst, const void* src) {
    asm volatile("cp.async.cg.shared.global [%0], [%1], 16;" :: "r"(dst), "l"(src));
}
#define CP_COMMIT() asm volatile("cp.async.commit_group;" ::: "memory")
#define CP_WAITG(n) asm volatile("cp.async.wait_group %0;" :: "n"(n) : "memory")

// vectorized global float reductions (PTX ISA 8.1+, sm_90+)
__device__ __forceinline__ void red_add_v4(float* p, float x0, float x1, float x2, float x3) {
    asm volatile("red.global.add.v4.f32 [%0], {%1, %2, %3, %4};"
                 :: "l"(p), "f"(x0), "f"(x1), "f"(x2), "f"(x3) : "memory");
}
__device__ __forceinline__ void red_add_v2(float* p, float x0, float x1) {
    asm volatile("red.global.add.v2.f32 [%0], {%1, %2};"
                 :: "l"(p), "f"(x0), "f"(x1) : "memory");
}

__device__ __forceinline__ void split_fp16(float x, __half& h, __half& l) {
    h = __float2half(x);
    l = __float2half(x - __half2float(h));
}
// pack two fp16 and store as u32
__device__ __forceinline__ void sm_storeh2(void* p, float x0, float x1) {
    union { __half h[2]; uint32_t u; } q;
    q.h[0] = __float2half(x0);
    q.h[1] = __float2half(x1);
    *(uint32_t*)p = q.u;
}

// ---------------- kernel 0: zero scratch ----------------
__global__ __launch_bounds__(256) void zero_kernel() {
    const int tot = Nn * 128 + Nn * 128 + Nn;
    for (int i = blockIdx.x * blockDim.x + threadIdx.x; i < tot; i += gridDim.x * blockDim.x) {
        if (i < Nn * 128) g_maggr[i] = 0.f;
        else if (i < 2 * Nn * 128) g_paggr[i - Nn * 128] = 0.f;
        else g_deg[i - 2 * Nn * 128] = 0.f;
    }
}

// ---------------- kernel 1: fp16 s + transpose/split weights ----------------
__global__ __launch_bounds__(256) void prep_kernel(
    const float* __restrict__ s, const float* __restrict__ W1,
    const float* __restrict__ W2, const float* __restrict__ P1)
{
    const int R0 = Nn * 128, R1 = 128 * 320, R2 = 128 * 128, R3 = 128 * 128;
    const int T = R0 + R1 + R2 + R3;
    for (int i = blockIdx.x * blockDim.x + threadIdx.x; i < T; i += gridDim.x * blockDim.x) {
        if (i < R0) {
            g_Sh[i] = __float2half(s[i]);
        } else if (i < R0 + R1) {
            int j = i - R0, n = j / 320, k = j % 320;
            float w = (k < 272) ? W1[k * 128 + n] : 0.f;
            split_fp16(w, g_W1Thi[j], g_W1Tlo[j]);
        } else if (i < R0 + R1 + R2) {
            int j = i - R0 - R1, n = j >> 7, k = j & 127;
            split_fp16(W2[k * 128 + n], g_W2Thi[j], g_W2Tlo[j]);
        } else {
            int j = i - R0 - R1 - R2, n = j >> 7, k = j & 127;
            split_fp16(P1[k * 128 + n], g_P1Thi[j], g_P1Tlo[j]);
        }
    }
}

// ---------------- kernel 2: per-edge MVLinear + edge_attr ----------------
__global__ __launch_bounds__(128) void edge_pre_kernel(
    const float* __restrict__ v, const int* __restrict__ ei,
    const float* __restrict__ Wv_w, const float* __restrict__ Wv_b)
{
    __shared__ float bufA[TBE][128];
    __shared__ float vij[TBE][128];
    __shared__ float attr[TBE][16];
    __shared__ float wv[1024], wvb[16];
    __shared__ int snd[TBE], rcv[TBE];

    const int tid = threadIdx.x;
    const int e0 = blockIdx.x * TBE;

    if (tid < TBE) { snd[tid] = ei[e0 + tid]; rcv[tid] = ei[Ee + e0 + tid]; }
    for (int i = tid; i < 1024; i += 128) wv[i] = Wv_w[i];
    if (tid < 16) wvb[tid] = Wv_b[tid];
    __syncthreads();

    for (int idx = tid; idx < TBE * 128; idx += 128) {
        int e = idx >> 7, z = idx & 127;
        bufA[e][z] = v[rcv[e] * 128 + z] - v[snd[e] * 128 + z];
    }
    if (tid < TBE) atomicAdd(&g_deg[snd[tid]], 1.0f);
    __syncthreads();

    for (int idx = tid; idx < TBE * 128; idx += 128) {
        int e = idx >> 7, z = idx & 127, o = z >> 3, bl = z & 7;
        int g = c_grade[bl];
        float acc = (bl == 0) ? wvb[o] : 0.f;
        #pragma unroll
        for (int c = 0; c < 16; c++) acc += bufA[e][c * 8 + bl] * wv[o * 64 + c * 4 + g];
        vij[e][z] = acc;
    }
    __syncthreads();

    for (int idx = tid; idx < TBE * 16; idx += 128) {
        int e = idx >> 4, o = idx & 15;
        float acc = 0.f;
        #pragma unroll
        for (int bl = 0; bl < 8; bl++) { float x = vij[e][o * 8 + bl]; acc += x * x; }
        attr[e][o] = acc;
    }
    __syncthreads();

    for (int idx = tid; idx < TBE * 128; idx += 128) {
        int e = idx >> 7, z = idx & 127;
        g_vij[(size_t)(e0 + e) * 128 + z] = vij[e][z];
    }
    for (int idx = tid; idx < TBE * 64; idx += 128) {
        int e = idx >> 6, z = idx & 63;
        float x = (z < 16) ? attr[e][z] : 0.f;
        g_EA[(size_t)(e0 + e) * 64 + z] = __float2half(x);
    }
}

// ---------------- fused 3-GEMM edge kernel (M=64, fp16 2-pass, 2 CTAs/SM) ----------------
// CTA = 64 edges, 256 threads = 8 warps: rw = w&1 (rows rw*32..+32),
// cw = w>>1 (cols cw*32..+32). acc 32x32 per warp = 32 fp32 regs.
// A rounded to fp16 (single), B split fp16 hi/lo; D = A*Bhi + A*Blo (fp32 acc).
// 3-stage ring (20KB/stage: [A 4K | Bhi 8K | Blo 8K]); per-chunk order
// wait -> sync -> prefetch(c+2) -> mma(c).
#define RINGO   0
#define SHMO    61440
#define SP2O    77824
#define SB1O    86016
#define SB2O    86528
#define SB3O    87040
#define SPB2O   87552
#define SSNDO   87616
#define SRCVO   87872
#define FUSED_SMEM 88128

__global__ __launch_bounds__(256, 2) void fused_gemm_kernel(
    const int* __restrict__ ei, const float* __restrict__ b1,
    const float* __restrict__ b2, const float* __restrict__ pb1,
    const float* __restrict__ P2, const float* __restrict__ pb2)
{
    extern __shared__ __align__(128) unsigned char smem[];
    const int tid = threadIdx.x;
    const int lane = tid & 31, w = tid >> 5;
    const int rw = w & 1, cw = w >> 1;
    const int grp = lane >> 2, qid = lane & 3;
    const int e0 = blockIdx.x * 64;
    const uint32_t usm = smem_u32(smem);

    int* ssnd = (int*)(smem + SSNDO);
    int* srcv = (int*)(smem + SRCVO);
    float* sb1 = (float*)(smem + SB1O);
    float* sb2 = (float*)(smem + SB2O);
    float* sb3 = (float*)(smem + SB3O);
    float* sP2 = (float*)(smem + SP2O);
    float* spb2 = (float*)(smem + SPB2O);

    if (tid < 64) {
        ssnd[tid] = ei[e0 + tid];
        srcv[tid] = ei[Ee + e0 + tid];
    }
    if (tid < 128) {
        sb1[tid] = b1[tid];
        sb2[tid] = b2[tid];
        sb3[tid] = pb1[tid];
    }
    for (int i = tid; i < 2048; i += 256) sP2[i] = P2[i];
    if (tid < 16) spb2[tid] = pb2[tid];
    __syncthreads();

    float acc[2][4][4];

    const int prow = tid >> 2;          // A row 0..63
    const int pkb = (tid & 3) * 16;     // byte offset in 64B row
    const int brow = tid >> 1;          // B row 0..127
    const int bkb = (tid & 1) * 32;     // byte offset (2x 16B)

    // phase-1 prefetch: chunk c of K=320 into ring stage s
    auto prefetch1 = [&](int c, int s) {
        const uint32_t st = usm + RINGO + s * 20480;
        const uint32_t so = st + sw_off(prow, pkb);
        if (c < 8) {
            int node = (c < 4) ? ssnd[prow] : srcv[prow];
            size_t off = (size_t)node * 128 + (c & 3) * 32;
            cpa16(so, (const char*)(g_Sh + off) + pkb);
        } else {
            size_t off = (size_t)(e0 + prow) * 64 + (c - 8) * 32;
            cpa16(so, (const char*)(g_EA + off) + pkb);
        }
        size_t o = (size_t)brow * 320 + c * 32;
        const char* bh = (const char*)(g_W1Thi + o);
        const char* bl = (const char*)(g_W1Tlo + o);
        uint32_t d0 = st + 4096 + sw_off(brow, bkb);
        uint32_t d1 = st + 4096 + sw_off(brow, bkb + 16);
        cpa16(d0, bh + bkb);
        cpa16(d1, bh + bkb + 16);
        cpa16(d0 + 8192, bl + bkb);
        cpa16(d1 + 8192, bl + bkb + 16);
    };

    // phase-2/3 prefetch: 32-k B-only chunk into ring stage s
    auto prefetch23 = [&](int phase, int c, int s) {
        const uint32_t st = usm + RINGO + s * 20480;
        const __half* Whi = (phase == 2) ? g_W2Thi : g_P1Thi;
        const __half* Wlo = (phase == 2) ? g_W2Tlo : g_P1Tlo;
        size_t o = (size_t)brow * 128 + c * 32;
        uint32_t d0 = st + 4096 + sw_off(brow, bkb);
        uint32_t d1 = st + 4096 + sw_off(brow, bkb + 16);
        cpa16(d0, (const char*)(Whi + o) + bkb);
        cpa16(d1, (const char*)(Whi + o) + bkb + 16);
        cpa16(d0 + 8192, (const char*)(Wlo + o) + bkb);
        cpa16(d1 + 8192, (const char*)(Wlo + o) + bkb + 16);
    };

    // one 32-k chunk of MMAs (fp16 2-pass: A*Bhi + A*Blo), 32x32 warp tile
    auto chunk_mma = [&](uint32_t aB, uint32_t bHi, uint32_t bLo) {
        #pragma unroll
        for (int kk = 0; kk < 2; kk++) {
            uint32_t A[2][4];
            const int arow = rw * 32 + (lane & 15);
            const int akb = kk * 32 + ((lane >> 4) << 4);
            ldsm_x4(A[0], aB + sw_off(arow, akb));
            ldsm_x4(A[1], aB + sw_off(arow + 16, akb));
            const int brow0 = cw * 32 + (lane & 7) + ((lane >> 4) << 3);
            const int bkb2 = kk * 32 + ((lane & 8) ? 16 : 0);
            #pragma unroll
            for (int np = 0; np < 2; np++) {
                uint32_t bh[4], bl[4];
                ldsm_x4(bh, bHi + sw_off(brow0 + np * 16, bkb2));
                ldsm_x4(bl, bLo + sw_off(brow0 + np * 16, bkb2));
                #pragma unroll
                for (int h2 = 0; h2 < 2; h2++) {
                    const int n = np * 2 + h2;
                    #pragma unroll
                    for (int mt = 0; mt < 2; mt++) {
                        mma16816(acc[mt][n], A[mt], bh + 2 * h2);
                        mma16816(acc[mt][n], A[mt], bl + 2 * h2);
                    }
                }
            }
        }
    };

    auto zero_acc = [&]() {
        #pragma unroll
        for (int mt = 0; mt < 2; mt++)
            #pragma unroll
            for (int n = 0; n < 4; n++)
                #pragma unroll
                for (int q = 0; q < 4; q++) acc[mt][n][q] = 0.f;
    };

    // ================= phase 1 (10 chunks, K=320) =================
    zero_acc();
    prefetch1(0, 0); CP_COMMIT();
    prefetch1(1, 1); CP_COMMIT();
    #pragma unroll 1
    for (int c = 0; c < 10; c++) {
        if (c + 1 < 10) CP_WAITG(1);
        else CP_WAITG(0);
        __syncthreads();   // chunk c visible; all warps done mma(c-1)
        if (c + 2 < 10) { prefetch1(c + 2, (c + 2) % 3); CP_COMMIT(); }
        const uint32_t st = usm + RINGO + (c % 3) * 20480;
        chunk_mma(st, st + 4096, st + 12288);
    }
    // epilogue: relu + bias -> fp16 -> sHM (4 chunks of 4KB)
    #pragma unroll
    for (int mt = 0; mt < 2; mt++) {
        const int r0 = rw * 32 + mt * 16 + grp;
        #pragma unroll
        for (int n = 0; n < 4; n++) {
            const int cc = cw * 32 + n * 8 + qid * 2;
            const int ch = cc >> 5;
            const uint32_t kb = (uint32_t)(cc & 31) * 2;
            const float bb0 = sb1[cc], bb1 = sb1[cc + 1];
            unsigned char* base = smem + SHMO + ch * 4096;
            sm_storeh2(base + sw_off(r0, kb),
                       fmaxf(acc[mt][n][0] + bb0, 0.f), fmaxf(acc[mt][n][1] + bb1, 0.f));
            sm_storeh2(base + sw_off(r0 + 8, kb),
                       fmaxf(acc[mt][n][2] + bb0, 0.f), fmaxf(acc[mt][n][3] + bb1, 0.f));
        }
    }
    __syncthreads();

    // ================= phase 2 (4 chunks, K=128) =================
    zero_acc();
    prefetch23(2, 0, 0); CP_COMMIT();
    prefetch23(2, 1, 1); CP_COMMIT();
    #pragma unroll 1
    for (int c = 0; c < 4; c++) {
        if (c + 1 < 4) CP_WAITG(1);
        else CP_WAITG(0);
        __syncthreads();
        if (c + 2 < 4) { prefetch23(2, c + 2, (c + 2) % 3); CP_COMMIT(); }
        const uint32_t st = usm + RINGO + (c % 3) * 20480;
        const uint32_t aB = usm + SHMO + c * 4096;
        chunk_mma(aB, st + 4096, st + 12288);
    }
    __syncthreads();  // all warps done reading sHM before sM overwrites it
    #pragma unroll
    for (int mt = 0; mt < 2; mt++) {
        const int r0 = rw * 32 + mt * 16 + grp;
        const int rA = srcv[r0], rB = srcv[r0 + 8];
        #pragma unroll
        for (int n = 0; n < 4; n++) {
            const int cc = cw * 32 + n * 8 + qid * 2;
            const int ch = cc >> 5;
            const uint32_t kb = (uint32_t)(cc & 31) * 2;
            const float bb0 = sb2[cc], bb1 = sb2[cc + 1];
            float m00 = acc[mt][n][0] + bb0, m01 = acc[mt][n][1] + bb1;
            float m10 = acc[mt][n][2] + bb0, m11 = acc[mt][n][3] + bb1;
            red_add_v2(&g_maggr[(size_t)rA * 128 + cc], m00, m01);
            red_add_v2(&g_maggr[(size_t)rB * 128 + cc], m10, m11);
            unsigned char* base = smem + SHMO + ch * 4096;
            sm_storeh2(base + sw_off(r0, kb), m00, m01);
            sm_storeh2(base + sw_off(r0 + 8, kb), m10, m11);
        }
    }
    __syncthreads();

    // ================= phase 3 (4 chunks, K=128) =================
    zero_acc();
    prefetch23(3, 0, 0); CP_COMMIT();
    prefetch23(3, 1, 1); CP_COMMIT();
    #pragma unroll 1
    for (int c = 0; c < 4; c++) {
        if (c + 1 < 4) CP_WAITG(1);
        else CP_WAITG(0);
        __syncthreads();
        if (c + 2 < 4) { prefetch23(3, c + 2, (c + 2) % 3); CP_COMMIT(); }
        const uint32_t st = usm + RINGO + (c % 3) * 20480;
        const uint32_t aB = usm + SHMO + c * 4096;
        chunk_mma(aB, st + 4096, st + 12288);
    }
    __syncthreads();  // ring free for spm
    float* spm = (float*)(smem + RINGO);            // [cw][64][16] = 16KB
    float* spmT = (float*)(smem + RINGO + 16384);   // [64][16] = 4KB
    #pragma unroll
    for (int mt = 0; mt < 2; mt++) {
        #pragma unroll
        for (int half = 0; half < 2; half++) {
            const int r = rw * 32 + mt * 16 + grp + half * 8;
            float pm[16];
            #pragma unroll
            for (int o = 0; o < 16; o++) pm[o] = 0.f;
            #pragma unroll
            for (int n = 0; n < 4; n++) {
                const int cc = cw * 32 + n * 8 + qid * 2;
                float x0 = fmaxf(acc[mt][n][half * 2 + 0] + sb3[cc], 0.f);
                float x1 = fmaxf(acc[mt][n][half * 2 + 1] + sb3[cc + 1], 0.f);
                const float* w0 = sP2 + cc * 16;
                const float* w1 = w0 + 16;
                #pragma unroll
                for (int o = 0; o < 16; o++) pm[o] += x0 * w0[o] + x1 * w1[o];
            }
            #pragma unroll
            for (int o = 0; o < 16; o++) {
                pm[o] += __shfl_xor_sync(0xffffffffu, pm[o], 1);
                pm[o] += __shfl_xor_sync(0xffffffffu, pm[o], 2);
            }
            #pragma unroll
            for (int j = 0; j < 4; j++)
                spm[cw * 1024 + r * 16 + qid * 4 + j] = pm[qid * 4 + j];
        }
    }
    __syncthreads();
    #pragma unroll
    for (int j = 0; j < 4; j++) {
        const int e = tid + j * 256;
        const int r = e >> 4, o = e & 15;
        spmT[e] = spm[r * 16 + o] + spm[1024 + r * 16 + o]
                + spm[2048 + r * 16 + o] + spm[3072 + r * 16 + o] + spb2[o];
    }
    __syncthreads();
    {
        const int r = tid >> 2;
        const int zb = (tid & 3) * 32;
        const int rc = srcv[r];
        const float* vr = g_vij + (size_t)(e0 + r) * 128;
        #pragma unroll
        for (int z = zb; z < zb + 32; z += 4) {
            float4 vv = *(const float4*)(vr + z);
            float p = spmT[r * 16 + (z >> 3)];
            red_add_v4(&g_paggr[(size_t)rc * 128 + z],
                       vv.x * p, vv.y * p, vv.z * p, vv.w * p);
        }
    }
}

// ---------------- kernel: per-node update ----------------
__global__ __launch_bounds__(128) void node_kernel(
    const float* __restrict__ s, const float* __restrict__ v,
    const float* __restrict__ U1, const float* __restrict__ ub1,
    const float* __restrict__ U2, const float* __restrict__ ub2,
    const float* __restrict__ gl_w, const float* __restrict__ gl_b,
    const float* __restrict__ gr_w, const float* __restrict__ gr_b,
    const float* __restrict__ go_w, const float* __restrict__ go_b,
    const float* __restrict__ ln_a,
    float* __restrict__ out_s, float* __restrict__ out_v)
{
    __shared__ __align__(16) float y[TN][256];
    __shared__ __align__(16) float h[TN][128];
    __shared__ __align__(16) float p[TN][128];
    __shared__ __align__(16) float vo[TN][128];
    __shared__ float cn[TN][16];
    __shared__ float nrm[TN];
    __shared__ float dinv[TN];
    __shared__ float wl[1024], wr[1024], wo[2048];
    __shared__ float wlb[16], wrb[16], wob[16], lna[16];

    const int tid = threadIdx.x;
    const int n0 = blockIdx.x * TN;

    for (int i = tid; i < 1024; i += 128) { wl[i] = gl_w[i]; wr[i] = gr_w[i]; }
    for (int i = tid; i < 2048; i += 128) wo[i] = go_w[i];
    if (tid < 16) { wlb[tid] = gl_b[tid]; wrb[tid] = gr_b[tid];
                    wob[tid] = go_b[tid]; lna[tid] = ln_a[tid]; }
    if (tid < TN) dinv[tid] = rsqrtf(g_deg[n0 + tid]);
    __syncthreads();

    for (int idx = tid; idx < TN * 128; idx += 128) {
        int n = idx >> 7, c = idx & 127;
        y[n][c]       = s[(n0 + n) * 128 + c];
        y[n][128 + c] = g_maggr[(n0 + n) * 128 + c] * dinv[n];
        p[n][c]       = g_paggr[(n0 + n) * 128 + c] * dinv[n];
    }
    __syncthreads();

    {
        float acc[TN];
        float bb = ub1[tid];
        #pragma unroll
        for (int n = 0; n < TN; n++) acc[n] = bb;
        for (int k = 0; k < 256; k += 4) {
            float w0 = U1[(k + 0) * 128 + tid];
            float w1 = U1[(k + 1) * 128 + tid];
            float w2 = U1[(k + 2) * 128 + tid];
            float w3 = U1[(k + 3) * 128 + tid];
            #pragma unroll
            for (int n = 0; n < TN; n++) {
                float4 x = *(const float4*)&y[n][k];
                acc[n] += x.x * w0 + x.y * w1 + x.z * w2 + x.w * w3;
            }
        }
        #pragma unroll
        for (int n = 0; n < TN; n++) h[n][tid] = fmaxf(acc[n], 0.f);
    }
    __syncthreads();

    {
        float acc[TN];
        float bb = ub2[tid];
        #pragma unroll
        for (int n = 0; n < TN; n++) acc[n] = bb;
        for (int k = 0; k < 128; k += 4) {
            float w0 = U2[(k + 0) * 128 + tid];
            float w1 = U2[(k + 1) * 128 + tid];
            float w2 = U2[(k + 2) * 128 + tid];
            float w3 = U2[(k + 3) * 128 + tid];
            #pragma unroll
            for (int n = 0; n < TN; n++) {
                float4 x = *(const float4*)&h[n][k];
                acc[n] += x.x * w0 + x.y * w1 + x.z * w2 + x.w * w3;
            }
        }
        #pragma unroll
        for (int n = 0; n < TN; n++)
            out_s[(n0 + n) * 128 + tid] = y[n][tid] + acc[n];
    }
    __syncthreads();

    for (int idx = tid; idx < TN * 128; idx += 128) {
        int n = idx >> 7, z = idx & 127, o = z >> 3, bl = z & 7;
        int g = c_grade[bl];
        float al = (bl == 0) ? wlb[o] : 0.f;
        float ar = (bl == 0) ? wrb[o] : 0.f;
        #pragma unroll
        for (int c = 0; c < 16; c++) {
            float pv = p[n][c * 8 + bl];
            al += pv * wl[o * 64 + c * 4 + g];
            ar += pv * wr[o * 64 + c * 4 + g];
        }
        y[n][z] = al;
        y[n][128 + z] = ar;
    }
    __syncthreads();

    for (int idx = tid; idx < TN * 16; idx += 128) {
        int n = idx >> 4, c = idx & 15;
        float a[8], b[8], o8[8];
        #pragma unroll
        for (int i = 0; i < 8; i++) {
            a[i] = y[n][c * 8 + i];
            b[i] = y[n][128 + c * 8 + i];
            o8[i] = 0.f;
        }
        #pragma unroll
        for (int i = 0; i < 8; i++)
            #pragma unroll
            for (int j = 0; j < 8; j++)
                o8[RES[i][j]] += SGN[i][j] * a[i] * b[j];
        #pragma unroll
        for (int k = 0; k < 8; k++) h[n][c * 8 + k] = o8[k];
    }
    __syncthreads();

    for (int idx = tid; idx < TN * 128; idx += 128) {
        int n = idx >> 7, z = idx & 127, o = z >> 3, bl = z & 7;
        int g = c_grade[bl];
        float acc = (bl == 0) ? wob[o] : 0.f;
        #pragma unroll
        for (int c = 0; c < 16; c++)
            acc += h[n][c * 8 + bl] * wo[o * 128 + c * 4 + g];
        #pragma unroll
        for (int c = 0; c < 16; c++)
            acc += p[n][c * 8 + bl] * wo[o * 128 + (16 + c) * 4 + g];
        vo[n][z] = acc;
    }
    __syncthreads();

    for (int idx = tid; idx < TN * 16; idx += 128) {
        int n = idx >> 4, c = idx & 15;
        float acc = 0.f;
        #pragma unroll
        for (int bl = 0; bl < 8; bl++) { float x = vo[n][c * 8 + bl]; acc += x * x; }
        cn[n][c] = sqrtf(acc);
    }
    __syncthreads();
    if (tid < TN) {
        float acc = 0.f;
        #pragma unroll
        for (int c = 0; c < 16; c++) acc += cn[tid][c];
        nrm[tid] = acc * (1.f / 16.f) + 1e-6f;
    }
    __syncthreads();
    for (int idx = tid; idx < TN * 128; idx += 128) {
        int n = idx >> 7, z = idx & 127, c = z >> 3;
        out_v[(n0 + n) * 128 + z] = lna[c] * vo[n][z] / nrm[n] + v[(n0 + n) * 128 + z];
    }
}

// ---------------- launcher ----------------
extern "C" void kernel_launch(void* const* d_in, const int* in_sizes, int n_in,
                              void* d_out, int out_size) {
    const float* s     = (const float*)d_in[0];
    const float* v     = (const float*)d_in[1];
    const int*   ei    = (const int*)  d_in[2];
    const float* Wv_w  = (const float*)d_in[3];
    const float* Wv_b  = (const float*)d_in[4];
    const float* mn_W1 = (const float*)d_in[5];
    const float* mn_b1 = (const float*)d_in[6];
    const float* mn_W2 = (const float*)d_in[7];
    const float* mn_b2 = (const float*)d_in[8];
    const float* pn_W1 = (const float*)d_in[9];
    const float* pn_b1 = (const float*)d_in[10];
    const float* pn_W2 = (const float*)d_in[11];
    const float* pn_b2 = (const float*)d_in[12];
    const float* un_W1 = (const float*)d_in[13];
    const float* un_b1 = (const float*)d_in[14];
    const float* un_W2 = (const float*)d_in[15];
    const float* un_b2 = (const float*)d_in[16];
    const float* gl_w  = (const float*)d_in[17];
    const float* gl_b  = (const float*)d_in[18];
    const float* gr_w  = (const float*)d_in[19];
    const float* gr_b  = (const float*)d_in[20];
    const float* go_w  = (const float*)d_in[21];
    const float* go_b  = (const float*)d_in[22];
    const float* ln_a  = (const float*)d_in[23];
    float* out = (float*)d_out;

    cudaFuncSetAttribute(fused_gemm_kernel,
                         cudaFuncAttributeMaxDynamicSharedMemorySize, FUSED_SMEM);

    zero_kernel<<<2048, 256>>>();
    prep_kernel<<<2048, 256>>>(s, mn_W1, mn_W2, pn_W1);
    edge_pre_kernel<<<Ee / TBE, 128>>>(v, ei, Wv_w, Wv_b);
    fused_gemm_kernel<<<Ee / 64, 256, FUSED_SMEM>>>(ei, mn_b1, mn_b2, pn_b1, pn_W2, pn_b2);
    node_kernel<<<Nn / TN, 128>>>(s, v, un_W1, un_b1, un_W2, un_b2,
                                  gl_w, gl_b, gr_w, gr_b, go_w, go_b, ln_a,
                                  out, out + Nn * 128);
}

// round 17
// speedup vs baseline: 1.5278x; 1.5278x over previous
#include <cuda_runtime.h>
#include <cuda_fp16.h>
#include <cstdint>

#define Nn 20000
#define Ee 320000
#define TBE 16
#define TN  8

// ---------------- scratch (device globals; no allocation) ----------------
__device__ float g_maggr[Nn * 128];
__device__ float g_paggr[Nn * 128];
__device__ float g_deg[Nn];
__device__ float g_vij[(size_t)Ee * 128];
__device__ __half g_Sh[Nn * 128];
__device__ __half g_EA[(size_t)Ee * 64];
__device__ __half g_W1Thi[128 * 320], g_W1Tlo[128 * 320];
__device__ __half g_W2Thi[128 * 128], g_W2Tlo[128 * 128];
__device__ __half g_P1Thi[128 * 128], g_P1Tlo[128 * 128];

__constant__ int c_grade[8] = {0, 1, 1, 1, 2, 2, 2, 3};
__device__ constexpr int RES[8][8] = {
    {0,1,2,3,4,5,6,7},{1,0,4,5,2,3,7,6},{2,4,0,6,1,7,3,5},{3,5,6,0,7,1,2,4},
    {4,2,1,7,0,6,5,3},{5,3,7,1,6,0,4,2},{6,7,3,2,5,4,0,1},{7,6,5,4,3,2,1,0}};
__device__ constexpr float SGN[8][8] = {
    { 1, 1, 1, 1, 1, 1, 1, 1},{ 1, 1, 1, 1, 1, 1, 1, 1},
    { 1,-1, 1, 1,-1,-1, 1,-1},{ 1,-1,-1, 1, 1,-1,-1, 1},
    { 1,-1, 1, 1,-1,-1, 1,-1},{ 1,-1,-1, 1, 1,-1,-1, 1},
    { 1, 1,-1, 1,-1, 1,-1,-1},{ 1, 1,-1, 1,-1, 1,-1,-1}};

// ---------------- helpers ----------------
__device__ __forceinline__ uint32_t smem_u32(const void* p) {
    uint32_t a;
    asm("{ .reg .u64 t; cvta.to.shared.u64 t, %1; cvt.u32.u64 %0, t; }" : "=r"(a) : "l"(p));
    return a;
}
// 2 logical 64B rows packed per 128B physical row, SW128 XOR swizzle.
__device__ __forceinline__ uint32_t sw_off(int row, int kb) {
    uint32_t o = ((uint32_t)(row >> 1) << 7) | ((uint32_t)(row & 1) << 6) | (uint32_t)kb;
    return o ^ ((o >> 3) & 0x70);
}
__device__ __forceinline__ void ldsm_x4(uint32_t* r, uint32_t addr) {
    asm volatile("ldmatrix.sync.aligned.m8n8.x4.shared.b16 {%0,%1,%2,%3}, [%4];"
                 : "=r"(r[0]), "=r"(r[1]), "=r"(r[2]), "=r"(r[3]) : "r"(addr));
}
__device__ __forceinline__ void mma16816(float* c, const uint32_t* a, const uint32_t* b) {
    asm volatile("mma.sync.aligned.m16n8k16.row.col.f32.f16.f16.f32 "
                 "{%0,%1,%2,%3}, {%4,%5,%6,%7}, {%8,%9}, {%0,%1,%2,%3};"
                 : "+f"(c[0]), "+f"(c[1]), "+f"(c[2]), "+f"(c[3])
                 : "r"(a[0]), "r"(a[1]), "r"(a[2]), "r"(a[3]), "r"(b[0]), "r"(b[1]));
}
__device__ __forceinline__ void cpa16(uint32_t dst, const void* src) {
    asm volatile("cp.async.cg.shared.global [%0], [%1], 16;" :: "r"(dst), "l"(src));
}
#define CP_COMMIT() asm volatile("cp.async.commit_group;" ::: "memory")
#define CP_WAITG(n) asm volatile("cp.async.wait_group %0;" :: "n"(n) : "memory")

// vectorized global float reductions (PTX ISA 8.1+, sm_90+)
__device__ __forceinline__ void red_add_v4(float* p, float x0, float x1, float x2, float x3) {
    asm volatile("red.global.add.v4.f32 [%0], {%1, %2, %3, %4};"
                 :: "l"(p), "f"(x0), "f"(x1), "f"(x2), "f"(x3) : "memory");
}
__device__ __forceinline__ void red_add_v2(float* p, float x0, float x1) {
    asm volatile("red.global.add.v2.f32 [%0], {%1, %2};"
                 :: "l"(p), "f"(x0), "f"(x1) : "memory");
}

__device__ __forceinline__ void split_fp16(float x, __half& h, __half& l) {
    h = __float2half(x);
    l = __float2half(x - __half2float(h));
}
__device__ __forceinline__ void sm_storeh2(void* p, float x0, float x1) {
    union { __half h[2]; uint32_t u; } q;
    q.h[0] = __float2half(x0);
    q.h[1] = __float2half(x1);
    *(uint32_t*)p = q.u;
}

// ---------------- kernel 0: zero scratch ----------------
__global__ __launch_bounds__(256) void zero_kernel() {
    const int tot = Nn * 128 + Nn * 128 + Nn;
    for (int i = blockIdx.x * blockDim.x + threadIdx.x; i < tot; i += gridDim.x * blockDim.x) {
        if (i < Nn * 128) g_maggr[i] = 0.f;
        else if (i < 2 * Nn * 128) g_paggr[i - Nn * 128] = 0.f;
        else g_deg[i - 2 * Nn * 128] = 0.f;
    }
}

// ---------------- kernel 1: fp16 s + transpose/split weights ----------------
__global__ __launch_bounds__(256) void prep_kernel(
    const float* __restrict__ s, const float* __restrict__ W1,
    const float* __restrict__ W2, const float* __restrict__ P1)
{
    const int R0 = Nn * 128, R1 = 128 * 320, R2 = 128 * 128, R3 = 128 * 128;
    const int T = R0 + R1 + R2 + R3;
    for (int i = blockIdx.x * blockDim.x + threadIdx.x; i < T; i += gridDim.x * blockDim.x) {
        if (i < R0) {
            g_Sh[i] = __float2half(s[i]);
        } else if (i < R0 + R1) {
            int j = i - R0, n = j / 320, k = j % 320;
            float w = (k < 272) ? W1[k * 128 + n] : 0.f;
            split_fp16(w, g_W1Thi[j], g_W1Tlo[j]);
        } else if (i < R0 + R1 + R2) {
            int j = i - R0 - R1, n = j >> 7, k = j & 127;
            split_fp16(W2[k * 128 + n], g_W2Thi[j], g_W2Tlo[j]);
        } else {
            int j = i - R0 - R1 - R2, n = j >> 7, k = j & 127;
            split_fp16(P1[k * 128 + n], g_P1Thi[j], g_P1Tlo[j]);
        }
    }
}

// ---------------- kernel 2: per-edge MVLinear + edge_attr ----------------
__global__ __launch_bounds__(128) void edge_pre_kernel(
    const float* __restrict__ v, const int* __restrict__ ei,
    const float* __restrict__ Wv_w, const float* __restrict__ Wv_b)
{
    __shared__ float bufA[TBE][128];
    __shared__ float vij[TBE][128];
    __shared__ float attr[TBE][16];
    __shared__ float wv[1024], wvb[16];
    __shared__ int snd[TBE], rcv[TBE];

    const int tid = threadIdx.x;
    const int e0 = blockIdx.x * TBE;

    if (tid < TBE) { snd[tid] = ei[e0 + tid]; rcv[tid] = ei[Ee + e0 + tid]; }
    for (int i = tid; i < 1024; i += 128) wv[i] = Wv_w[i];
    if (tid < 16) wvb[tid] = Wv_b[tid];
    __syncthreads();

    for (int idx = tid; idx < TBE * 128; idx += 128) {
        int e = idx >> 7, z = idx & 127;
        bufA[e][z] = v[rcv[e] * 128 + z] - v[snd[e] * 128 + z];
    }
    if (tid < TBE) atomicAdd(&g_deg[snd[tid]], 1.0f);
    __syncthreads();

    for (int idx = tid; idx < TBE * 128; idx += 128) {
        int e = idx >> 7, z = idx & 127, o = z >> 3, bl = z & 7;
        int g = c_grade[bl];
        float acc = (bl == 0) ? wvb[o] : 0.f;
        #pragma unroll
        for (int c = 0; c < 16; c++) acc += bufA[e][c * 8 + bl] * wv[o * 64 + c * 4 + g];
        vij[e][z] = acc;
    }
    __syncthreads();

    for (int idx = tid; idx < TBE * 16; idx += 128) {
        int e = idx >> 4, o = idx & 15;
        float acc = 0.f;
        #pragma unroll
        for (int bl = 0; bl < 8; bl++) { float x = vij[e][o * 8 + bl]; acc += x * x; }
        attr[e][o] = acc;
    }
    __syncthreads();

    for (int idx = tid; idx < TBE * 128; idx += 128) {
        int e = idx >> 7, z = idx & 127;
        g_vij[(size_t)(e0 + e) * 128 + z] = vij[e][z];
    }
    for (int idx = tid; idx < TBE * 64; idx += 128) {
        int e = idx >> 6, z = idx & 63;
        float x = (z < 16) ? attr[e][z] : 0.f;
        g_EA[(size_t)(e0 + e) * 64 + z] = __float2half(x);
    }
}

// ---------------- fused 3-GEMM edge kernel (M=64, fp16 2-pass, R13 skeleton) ----------------
// CTA = 64 edges, 256 threads = 8 warps: rw = w&1 (rows rw*32..+32),
// cw = w>>1 (cols cw*32..+32). acc 32x32 per warp = 32 fp32 regs.
// STRUCTURE IDENTICAL TO R13: 2-stage 24KB ring (A fp16 at 0, [4096,8192)
// unused, Bhi 8192, Blo 16384), wait(0) -> sync -> prefetch(c+1) -> mma(c),
// sHM 8KB chunk stride (fp16 data in low 4KB). Only precision changed.
#define RINGO   0
#define SHMO    49152
#define SP2O    81920
#define SB1O    90112
#define SB2O    90624
#define SB3O    91136
#define SPB2O   91648
#define SSNDO   91712
#define SRCVO   91968
#define FUSED_SMEM 92224

__global__ __launch_bounds__(256, 2) void fused_gemm_kernel(
    const int* __restrict__ ei, const float* __restrict__ b1,
    const float* __restrict__ b2, const float* __restrict__ pb1,
    const float* __restrict__ P2, const float* __restrict__ pb2)
{
    extern __shared__ __align__(128) unsigned char smem[];
    const int tid = threadIdx.x;
    const int lane = tid & 31, w = tid >> 5;
    const int rw = w & 1, cw = w >> 1;
    const int grp = lane >> 2, qid = lane & 3;
    const int e0 = blockIdx.x * 64;
    const uint32_t usm = smem_u32(smem);

    int* ssnd = (int*)(smem + SSNDO);
    int* srcv = (int*)(smem + SRCVO);
    float* sb1 = (float*)(smem + SB1O);
    float* sb2 = (float*)(smem + SB2O);
    float* sb3 = (float*)(smem + SB3O);
    float* sP2 = (float*)(smem + SP2O);
    float* spb2 = (float*)(smem + SPB2O);

    if (tid < 64) {
        ssnd[tid] = ei[e0 + tid];
        srcv[tid] = ei[Ee + e0 + tid];
    }
    if (tid < 128) {
        sb1[tid] = b1[tid];
        sb2[tid] = b2[tid];
        sb3[tid] = pb1[tid];
    }
    for (int i = tid; i < 2048; i += 256) sP2[i] = P2[i];
    if (tid < 16) spb2[tid] = pb2[tid];
    __syncthreads();

    float acc[2][4][4];

    const int prow = tid >> 2;          // A row 0..63
    const int pkb = (tid & 3) * 16;     // byte offset in 64B row
    const int brow = tid >> 1;          // B row 0..127
    const int bkb = (tid & 1) * 32;     // byte offset (2x 16B each)

    // phase-1 prefetch: chunk c of K=320 into ring stage s
    auto prefetch1 = [&](int c, int s) {
        const uint32_t st = usm + RINGO + s * 24576;
        const uint32_t so = st + sw_off(prow, pkb);
        if (c < 8) {
            int node = (c < 4) ? ssnd[prow] : srcv[prow];
            size_t off = (size_t)node * 128 + (c & 3) * 32;
            cpa16(so, (const char*)(g_Sh + off) + pkb);
        } else {
            size_t off = (size_t)(e0 + prow) * 64 + (c - 8) * 32;
            cpa16(so, (const char*)(g_EA + off) + pkb);
        }
        size_t o = (size_t)brow * 320 + c * 32;
        const char* bh = (const char*)(g_W1Thi + o);
        const char* bl = (const char*)(g_W1Tlo + o);
        uint32_t d0 = st + 8192 + sw_off(brow, bkb);
        uint32_t d1 = st + 8192 + sw_off(brow, bkb + 16);
        cpa16(d0, bh + bkb);
        cpa16(d1, bh + bkb + 16);
        cpa16(d0 + 8192, bl + bkb);
        cpa16(d1 + 8192, bl + bkb + 16);
    };

    // phase-2/3 prefetch: 32-k B-only chunk into ring stage s
    auto prefetch23 = [&](int phase, int c, int s) {
        const uint32_t st = usm + RINGO + s * 24576;
        const __half* Whi = (phase == 2) ? g_W2Thi : g_P1Thi;
        const __half* Wlo = (phase == 2) ? g_W2Tlo : g_P1Tlo;
        size_t o = (size_t)brow * 128 + c * 32;
        uint32_t d0 = st + 8192 + sw_off(brow, bkb);
        uint32_t d1 = st + 8192 + sw_off(brow, bkb + 16);
        cpa16(d0, (const char*)(Whi + o) + bkb);
        cpa16(d1, (const char*)(Whi + o) + bkb + 16);
        cpa16(d0 + 8192, (const char*)(Wlo + o) + bkb);
        cpa16(d1 + 8192, (const char*)(Wlo + o) + bkb + 16);
    };

    // one 32-k chunk of MMAs (fp16 2-pass: A*Bhi + A*Blo), 32x32 warp tile
    auto chunk_mma = [&](uint32_t aB, uint32_t bHi, uint32_t bLo) {
        #pragma unroll
        for (int kk = 0; kk < 2; kk++) {
            uint32_t A[2][4];
            const int arow = rw * 32 + (lane & 15);
            const int akb = kk * 32 + ((lane >> 4) << 4);
            ldsm_x4(A[0], aB + sw_off(arow, akb));
            ldsm_x4(A[1], aB + sw_off(arow + 16, akb));
            const int brow0 = cw * 32 + (lane & 7) + ((lane >> 4) << 3);
            const int bkb2 = kk * 32 + ((lane & 8) ? 16 : 0);
            #pragma unroll
            for (int np = 0; np < 2; np++) {
                uint32_t bh[4], bl[4];
                ldsm_x4(bh, bHi + sw_off(brow0 + np * 16, bkb2));
                ldsm_x4(bl, bLo + sw_off(brow0 + np * 16, bkb2));
                #pragma unroll
                for (int h2 = 0; h2 < 2; h2++) {
                    const int n = np * 2 + h2;
                    #pragma unroll
                    for (int mt = 0; mt < 2; mt++) {
                        mma16816(acc[mt][n], A[mt], bh + 2 * h2);
                        mma16816(acc[mt][n], A[mt], bl + 2 * h2);
                    }
                }
            }
        }
    };

    auto zero_acc = [&]() {
        #pragma unroll
        for (int mt = 0; mt < 2; mt++)
            #pragma unroll
            for (int n = 0; n < 4; n++)
                #pragma unroll
                for (int q = 0; q < 4; q++) acc[mt][n][q] = 0.f;
    };

    // ================= phase 1 (10 chunks, K=320) =================
    zero_acc();
    prefetch1(0, 0); CP_COMMIT();
    #pragma unroll 1
    for (int c = 0; c < 10; c++) {
        CP_WAITG(0);
        __syncthreads();   // chunk c visible; all warps done mma(c-1)
        if (c + 1 < 10) { prefetch1(c + 1, (c + 1) & 1); CP_COMMIT(); }
        const uint32_t st = usm + RINGO + (c & 1) * 24576;
        chunk_mma(st, st + 8192, st + 16384);
    }
    // epilogue: relu + bias -> fp16 -> sHM (4 chunks, 8KB stride, data in low 4KB)
    #pragma unroll
    for (int mt = 0; mt < 2; mt++) {
        const int r0 = rw * 32 + mt * 16 + grp;
        #pragma unroll
        for (int n = 0; n < 4; n++) {
            const int cc = cw * 32 + n * 8 + qid * 2;
            const int ch = cc >> 5;
            const uint32_t kb = (uint32_t)(cc & 31) * 2;
            const float bb0 = sb1[cc], bb1 = sb1[cc + 1];
            unsigned char* base = smem + SHMO + ch * 8192;
            sm_storeh2(base + sw_off(r0, kb),
                       fmaxf(acc[mt][n][0] + bb0, 0.f), fmaxf(acc[mt][n][1] + bb1, 0.f));
            sm_storeh2(base + sw_off(r0 + 8, kb),
                       fmaxf(acc[mt][n][2] + bb0, 0.f), fmaxf(acc[mt][n][3] + bb1, 0.f));
        }
    }
    __syncthreads();

    // ================= phase 2 (4 chunks, K=128) =================
    zero_acc();
    prefetch23(2, 0, 0); CP_COMMIT();
    #pragma unroll 1
    for (int c = 0; c < 4; c++) {
        CP_WAITG(0);
        __syncthreads();
        if (c + 1 < 4) { prefetch23(2, c + 1, (c + 1) & 1); CP_COMMIT(); }
        const uint32_t st = usm + RINGO + (c & 1) * 24576;
        const uint32_t aB = usm + SHMO + c * 8192;
        chunk_mma(aB, st + 8192, st + 16384);
    }
    __syncthreads();  // all warps done reading sHM before sM overwrites it
    #pragma unroll
    for (int mt = 0; mt < 2; mt++) {
        const int r0 = rw * 32 + mt * 16 + grp;
        const int rA = srcv[r0], rB = srcv[r0 + 8];
        #pragma unroll
        for (int n = 0; n < 4; n++) {
            const int cc = cw * 32 + n * 8 + qid * 2;
            const int ch = cc >> 5;
            const uint32_t kb = (uint32_t)(cc & 31) * 2;
            const float bb0 = sb2[cc], bb1 = sb2[cc + 1];
            float m00 = acc[mt][n][0] + bb0, m01 = acc[mt][n][1] + bb1;
            float m10 = acc[mt][n][2] + bb0, m11 = acc[mt][n][3] + bb1;
            red_add_v2(&g_maggr[(size_t)rA * 128 + cc], m00, m01);
            red_add_v2(&g_maggr[(size_t)rB * 128 + cc], m10, m11);
            unsigned char* base = smem + SHMO + ch * 8192;
            sm_storeh2(base + sw_off(r0, kb), m00, m01);
            sm_storeh2(base + sw_off(r0 + 8, kb), m10, m11);
        }
    }
    __syncthreads();

    // ================= phase 3 (4 chunks, K=128) =================
    zero_acc();
    prefetch23(3, 0, 0); CP_COMMIT();
    #pragma unroll 1
    for (int c = 0; c < 4; c++) {
        CP_WAITG(0);
        __syncthreads();
        if (c + 1 < 4) { prefetch23(3, c + 1, (c + 1) & 1); CP_COMMIT(); }
        const uint32_t st = usm + RINGO + (c & 1) * 24576;
        const uint32_t aB = usm + SHMO + c * 8192;
        chunk_mma(aB, st + 8192, st + 16384);
    }
    __syncthreads();  // ring free for spm
    float* spm = (float*)(smem + RINGO);            // [cw][64][16] = 16KB
    float* spmT = (float*)(smem + RINGO + 16384);   // [64][16] = 4KB
    #pragma unroll
    for (int mt = 0; mt < 2; mt++) {
        #pragma unroll
        for (int half = 0; half < 2; half++) {
            const int r = rw * 32 + mt * 16 + grp + half * 8;
            float pm[16];
            #pragma unroll
            for (int o = 0; o < 16; o++) pm[o] = 0.f;
            #pragma unroll
            for (int n = 0; n < 4; n++) {
                const int cc = cw * 32 + n * 8 + qid * 2;
                float x0 = fmaxf(acc[mt][n][half * 2 + 0] + sb3[cc], 0.f);
                float x1 = fmaxf(acc[mt][n][half * 2 + 1] + sb3[cc + 1], 0.f);
                const float* w0 = sP2 + cc * 16;
                const float* w1 = w0 + 16;
                #pragma unroll
                for (int o = 0; o < 16; o++) pm[o] += x0 * w0[o] + x1 * w1[o];
            }
            #pragma unroll
            for (int o = 0; o < 16; o++) {
                pm[o] += __shfl_xor_sync(0xffffffffu, pm[o], 1);
                pm[o] += __shfl_xor_sync(0xffffffffu, pm[o], 2);
            }
            #pragma unroll
            for (int j = 0; j < 4; j++)
                spm[cw * 1024 + r * 16 + qid * 4 + j] = pm[qid * 4 + j];
        }
    }
    __syncthreads();
    #pragma unroll
    for (int j = 0; j < 4; j++) {
        const int e = tid + j * 256;
        const int r = e >> 4, o = e & 15;
        spmT[e] = spm[r * 16 + o] + spm[1024 + r * 16 + o]
                + spm[2048 + r * 16 + o] + spm[3072 + r * 16 + o] + spb2[o];
    }
    __syncthreads();
    {
        const int r = tid >> 2;
        const int zb = (tid & 3) * 32;
        const int rc = srcv[r];
        const float* vr = g_vij + (size_t)(e0 + r) * 128;
        #pragma unroll
        for (int z = zb; z < zb + 32; z += 4) {
            float4 vv = *(const float4*)(vr + z);
            float p = spmT[r * 16 + (z >> 3)];
            red_add_v4(&g_paggr[(size_t)rc * 128 + z],
                       vv.x * p, vv.y * p, vv.z * p, vv.w * p);
        }
    }
}

// ---------------- kernel: per-node update ----------------
__global__ __launch_bounds__(128) void node_kernel(
    const float* __restrict__ s, const float* __restrict__ v,
    const float* __restrict__ U1, const float* __restrict__ ub1,
    const float* __restrict__ U2, const float* __restrict__ ub2,
    const float* __restrict__ gl_w, const float* __restrict__ gl_b,
    const float* __restrict__ gr_w, const float* __restrict__ gr_b,
    const float* __restrict__ go_w, const float* __restrict__ go_b,
    const float* __restrict__ ln_a,
    float* __restrict__ out_s, float* __restrict__ out_v)
{
    __shared__ __align__(16) float y[TN][256];
    __shared__ __align__(16) float h[TN][128];
    __shared__ __align__(16) float p[TN][128];
    __shared__ __align__(16) float vo[TN][128];
    __shared__ float cn[TN][16];
    __shared__ float nrm[TN];
    __shared__ float dinv[TN];
    __shared__ float wl[1024], wr[1024], wo[2048];
    __shared__ float wlb[16], wrb[16], wob[16], lna[16];

    const int tid = threadIdx.x;
    const int n0 = blockIdx.x * TN;

    for (int i = tid; i < 1024; i += 128) { wl[i] = gl_w[i]; wr[i] = gr_w[i]; }
    for (int i = tid; i < 2048; i += 128) wo[i] = go_w[i];
    if (tid < 16) { wlb[tid] = gl_b[tid]; wrb[tid] = gr_b[tid];
                    wob[tid] = go_b[tid]; lna[tid] = ln_a[tid]; }
    if (tid < TN) dinv[tid] = rsqrtf(g_deg[n0 + tid]);
    __syncthreads();

    for (int idx = tid; idx < TN * 128; idx += 128) {
        int n = idx >> 7, c = idx & 127;
        y[n][c]       = s[(n0 + n) * 128 + c];
        y[n][128 + c] = g_maggr[(n0 + n) * 128 + c] * dinv[n];
        p[n][c]       = g_paggr[(n0 + n) * 128 + c] * dinv[n];
    }
    __syncthreads();

    {
        float acc[TN];
        float bb = ub1[tid];
        #pragma unroll
        for (int n = 0; n < TN; n++) acc[n] = bb;
        for (int k = 0; k < 256; k += 4) {
            float w0 = U1[(k + 0) * 128 + tid];
            float w1 = U1[(k + 1) * 128 + tid];
            float w2 = U1[(k + 2) * 128 + tid];
            float w3 = U1[(k + 3) * 128 + tid];
            #pragma unroll
            for (int n = 0; n < TN; n++) {
                float4 x = *(const float4*)&y[n][k];
                acc[n] += x.x * w0 + x.y * w1 + x.z * w2 + x.w * w3;
            }
        }
        #pragma unroll
        for (int n = 0; n < TN; n++) h[n][tid] = fmaxf(acc[n], 0.f);
    }
    __syncthreads();

    {
        float acc[TN];
        float bb = ub2[tid];
        #pragma unroll
        for (int n = 0; n < TN; n++) acc[n] = bb;
        for (int k = 0; k < 128; k += 4) {
            float w0 = U2[(k + 0) * 128 + tid];
            float w1 = U2[(k + 1) * 128 + tid];
            float w2 = U2[(k + 2) * 128 + tid];
            float w3 = U2[(k + 3) * 128 + tid];
            #pragma unroll
            for (int n = 0; n < TN; n++) {
                float4 x = *(const float4*)&h[n][k];
                acc[n] += x.x * w0 + x.y * w1 + x.z * w2 + x.w * w3;
            }
        }
        #pragma unroll
        for (int n = 0; n < TN; n++)
            out_s[(n0 + n) * 128 + tid] = y[n][tid] + acc[n];
    }
    __syncthreads();

    for (int idx = tid; idx < TN * 128; idx += 128) {
        int n = idx >> 7, z = idx & 127, o = z >> 3, bl = z & 7;
        int g = c_grade[bl];
        float al = (bl == 0) ? wlb[o] : 0.f;
        float ar = (bl == 0) ? wrb[o] : 0.f;
        #pragma unroll
        for (int c = 0; c < 16; c++) {
            float pv = p[n][c * 8 + bl];
            al += pv * wl[o * 64 + c * 4 + g];
            ar += pv * wr[o * 64 + c * 4 + g];
        }
        y[n][z] = al;
        y[n][128 + z] = ar;
    }
    __syncthreads();

    for (int idx = tid; idx < TN * 16; idx += 128) {
        int n = idx >> 4, c = idx & 15;
        float a[8], b[8], o8[8];
        #pragma unroll
        for (int i = 0; i < 8; i++) {
            a[i] = y[n][c * 8 + i];
            b[i] = y[n][128 + c * 8 + i];
            o8[i] = 0.f;
        }
        #pragma unroll
        for (int i = 0; i < 8; i++)
            #pragma unroll
            for (int j = 0; j < 8; j++)
                o8[RES[i][j]] += SGN[i][j] * a[i] * b[j];
        #pragma unroll
        for (int k = 0; k < 8; k++) h[n][c * 8 + k] = o8[k];
    }
    __syncthreads();

    for (int idx = tid; idx < TN * 128; idx += 128) {
        int n = idx >> 7, z = idx & 127, o = z >> 3, bl = z & 7;
        int g = c_grade[bl];
        float acc = (bl == 0) ? wob[o] : 0.f;
        #pragma unroll
        for (int c = 0; c < 16; c++)
            acc += h[n][c * 8 + bl] * wo[o * 128 + c * 4 + g];
        #pragma unroll
        for (int c = 0; c < 16; c++)
            acc += p[n][c * 8 + bl] * wo[o * 128 + (16 + c) * 4 + g];
        vo[n][z] = acc;
    }
    __syncthreads();

    for (int idx = tid; idx < TN * 16; idx += 128) {
        int n = idx >> 4, c = idx & 15;
        float acc = 0.f;
        #pragma unroll
        for (int bl = 0; bl < 8; bl++) { float x = vo[n][c * 8 + bl]; acc += x * x; }
        cn[n][c] = sqrtf(acc);
    }
    __syncthreads();
    if (tid < TN) {
        float acc = 0.f;
        #pragma unroll
        for (int c = 0; c < 16; c++) acc += cn[tid][c];
        nrm[tid] = acc * (1.f / 16.f) + 1e-6f;
    }
    __syncthreads();
    for (int idx = tid; idx < TN * 128; idx += 128) {
        int n = idx >> 7, z = idx & 127, c = z >> 3;
        out_v[(n0 + n) * 128 + z] = lna[c] * vo[n][z] / nrm[n] + v[(n0 + n) * 128 + z];
    }
}

// ---------------- launcher ----------------
extern "C" void kernel_launch(void* const* d_in, const int* in_sizes, int n_in,
                              void* d_out, int out_size) {
    const float* s     = (const float*)d_in[0];
    const float* v     = (const float*)d_in[1];
    const int*   ei    = (const int*)  d_in[2];
    const float* Wv_w  = (const float*)d_in[3];
    const float* Wv_b  = (const float*)d_in[4];
    const float* mn_W1 = (const float*)d_in[5];
    const float* mn_b1 = (const float*)d_in[6];
    const float* mn_W2 = (const float*)d_in[7];
    const float* mn_b2 = (const float*)d_in[8];
    const float* pn_W1 = (const float*)d_in[9];
    const float* pn_b1 = (const float*)d_in[10];
    const float* pn_W2 = (const float*)d_in[11];
    const float* pn_b2 = (const float*)d_in[12];
    const float* un_W1 = (const float*)d_in[13];
    const float* un_b1 = (const float*)d_in[14];
    const float* un_W2 = (const float*)d_in[15];
    const float* un_b2 = (const float*)d_in[16];
    const float* gl_w  = (const float*)d_in[17];
    const float* gl_b  = (const float*)d_in[18];
    const float* gr_w  = (const float*)d_in[19];
    const float* gr_b  = (const float*)d_in[20];
    const float* go_w  = (const float*)d_in[21];
    const float* go_b  = (const float*)d_in[22];
    const float* ln_a  = (const float*)d_in[23];
    float* out = (float*)d_out;

    cudaFuncSetAttribute(fused_gemm_kernel,
                         cudaFuncAttributeMaxDynamicSharedMemorySize, FUSED_SMEM);

    zero_kernel<<<2048, 256>>>();
    prep_kernel<<<2048, 256>>>(s, mn_W1, mn_W2, pn_W1);
    edge_pre_kernel<<<Ee / TBE, 128>>>(v, ei, Wv_w, Wv_b);
    fused_gemm_kernel<<<Ee / 64, 256, FUSED_SMEM>>>(ei, mn_b1, mn_b2, pn_b1, pn_W2, pn_b2);
    node_kernel<<<Nn / TN, 128>>>(s, v, un_W1, un_b1, un_W2, un_b2,
                                  gl_w, gl_b, gr_w, gr_b, go_w, go_b, ln_a,
                                  out, out + Nn * 128);
}